// round 15
// baseline (speedup 1.0000x reference)
#include <cuda_runtime.h>
#include <cstdint>

#define NITEMS 4096
#define TPB    1024
#define NWARP  32
#define EPT    4           // elements per thread
#define CAP    600.0f
#define MU     1e-3f
#define MAXIT  16
#define LAM0   0.82f       // ensemble warm start (integral estimate lam* ~ 0.83)
#define PHI_EMIT 0.15f     // exit gate; 2nd-order emit absorbs dlam up to ~4e-4

__device__ __forceinline__ float frcp(float v) {
    float r;
    asm("rcp.approx.ftz.f32 %0, %1;" : "=f"(r) : "f"(v));
    return r;
}
__device__ __forceinline__ float frsq(float v) {
    float r;
    asm("rsqrt.approx.ftz.f32 %0, %1;" : "=f"(r) : "f"(v));
    return r;
}

__device__ __forceinline__ float wsum32(float v) {
#pragma unroll
    for (int o = 16; o > 0; o >>= 1) v += __shfl_xor_sync(0xffffffffu, v, o);
    return v;
}

// interior root of g x^2 - (g+2mu) x + mu = 0, cancellation-free:
//   t(a) = 2mu / (a + 2mu + sqrt(a^2+4mu^2)),  a = |g|;  x = g>=0 ? t : 1-t
// nd = -dx/dg = t * rden * (1 + a/D) = 1/H  (same value for both signs)
__device__ __forceinline__ void xofg(float g, float& x, float& nd) {
    const float a    = fabsf(g);
    const float u    = fmaf(a, a, 4.0f * MU * MU);
    const float rD   = frsq(u);
    const float den  = fmaf(u, rD, a + 2.0f * MU);   // a + 2mu + sqrt(u)
    const float rden = frcp(den);
    const float t    = (2.0f * MU) * rden;
    x  = (g >= 0.0f) ? t : 1.0f - t;
    nd = (t * rden) * fmaf(a, rD, 1.0f);
}

__global__ void __launch_bounds__(TPB, 1)
ipm_kernel(const float* __restrict__ costs,
           const float* __restrict__ wglob,
           float* __restrict__ out)
{
    __shared__ float sR[2][2][NWARP];       // [parity][s1|s2][warp]

    const int tid = threadIdx.x, lane = tid & 31, wid = tid >> 5;

    float cA[EPT], wA[EPT], xA[EPT], ndA[EPT];   // all state in registers
    float lam = LAM0, lo = -30.0f, hi = 30.0f, dlam = 0.0f;
    float s1 = 0.0f, s2 = 0.0f;

    // ---- load (one float4 each) + fused first evaluation at LAM0 -----------
    {
        const float4 c4 = ((const float4*)(costs + (size_t)blockIdx.x * NITEMS))[tid];
        const float4 w4 = ((const float4*)wglob)[tid];
        cA[0] = c4.x; cA[1] = c4.y; cA[2] = c4.z; cA[3] = c4.w;
        wA[0] = w4.x; wA[1] = w4.y; wA[2] = w4.z; wA[3] = w4.w;
#pragma unroll
        for (int i = 0; i < EPT; i++) {
            float x, nd;
            xofg(fmaf(lam, wA[i], -cA[i]), x, nd);
            xA[i] = x; ndA[i] = nd;
            s1 = fmaf(wA[i], x, s1);
            s2 = fmaf(wA[i] * wA[i], nd, s2);
        }
    }

    // ---- 1-D safeguarded (bracketed) Newton on lambda ----------------------
    //   phi(lam) = sum w*x(lam) - CAP,  phi' = -s2
    // Exit when |phi| < PHI_EMIT; the pending Newton increment dlam = phi/s2
    // is applied per-element at emit with a 2nd-order Taylor correction.
#pragma unroll 1
    for (int it = 0; it < MAXIT; ++it) {
        float r1 = wsum32(s1), r2 = wsum32(s2);
        const int par = it & 1;
        if (lane == 0) { sR[par][0][wid] = r1; sR[par][1][wid] = r2; }
        __syncthreads();
        r1 = wsum32(sR[par][0][lane]);      // 32 partials -> full block sum,
        r2 = wsum32(sR[par][1][lane]);      // identical in all threads

        const float phi  = r1 - CAP;
        const float step = phi * frcp(r2);  // Newton increment
        if (fabsf(phi) < PHI_EMIT || it == MAXIT - 1) {
            dlam = step;                    // applied at emit (2nd order)
            break;                          // xA/ndA match current lam
        }
        if (phi > 0.0f) lo = lam; else hi = lam;   // phi monotone decreasing
        float ln = lam + step;
        if (!(ln > lo && ln < hi)) ln = 0.5f * (lo + hi);
        lam = ln;

        // next evaluation: everything from registers
        s1 = 0.0f; s2 = 0.0f;
#pragma unroll
        for (int i = 0; i < EPT; i++) {
            float x, nd;
            xofg(fmaf(lam, wA[i], -cA[i]), x, nd);
            xA[i] = x; ndA[i] = nd;
            s1 = fmaf(wA[i], x, s1);
            s2 = fmaf(wA[i] * wA[i], nd, s2);
        }
    }

    // ---- emit: out = x - dlam*w*nd + 0.5*(dlam*w)^2*x''  -------------------
    //   x'' = 2*nd*(t1 - g*nd)/Fx,  t1 = 2x-1,  Fx = g*t1 - 2mu (|Fx| >= 2mu)
    {
        float4 o;
        float r[EPT];
#pragma unroll
        for (int i = 0; i < EPT; i++) {
            const float g   = fmaf(lam, wA[i], -cA[i]);
            const float wd  = wA[i] * dlam;
            const float x   = xA[i], nd = ndA[i];
            const float t1  = fmaf(2.0f, x, -1.0f);
            const float Fx  = fmaf(g, t1, -2.0f * MU);
            const float num = 2.0f * nd * fmaf(-g, nd, t1);
            const float xpp = num * frcp(Fx);
            const float o1  = fmaf(-wd, nd, x);
            r[i] = fmaf(0.5f * wd * wd, xpp, o1);
        }
        o.x = r[0]; o.y = r[1]; o.z = r[2]; o.w = r[3];
        ((float4*)(out + (size_t)blockIdx.x * NITEMS))[tid] = o;
    }
}

extern "C" void kernel_launch(void* const* d_in, const int* in_sizes, int n_in,
                              void* d_out, int out_size)
{
    const float* costs = (const float*)d_in[0];
    const float* wv    = (const float*)d_in[1];
    int costs_elems = in_sizes[0];
    if (n_in >= 2 && in_sizes[0] == NITEMS && in_sizes[1] > NITEMS) {
        costs = (const float*)d_in[1];
        wv    = (const float*)d_in[0];
        costs_elems = in_sizes[1];
    }
    const int B = costs_elems / NITEMS;
    ipm_kernel<<<B, TPB>>>(costs, wv, (float*)d_out);
}